// round 2
// baseline (speedup 1.0000x reference)
#include <cuda_runtime.h>

#define Lc 512
#define Bc 32
#define Tc 48

__device__ float g_llh[Bc];

// 2^e as float; e <= -127 -> 0 (negligible contribution), e in [-126,127] exact.
__device__ __forceinline__ float pow2i(int e) {
    e = (e < -127) ? -127 : e;
    return __int_as_float((e + 127) << 23);
}

// ---------------------------------------------------------------------------
// One block per batch; 192 threads = (t=48) x (c=4).
// Scaled-linear semi-CRF forward recursion:
//   P_j[t] = exp(alpha_j[t]) * 2^{-C_{j-1}},  C integer shift tracked via
//   exponent bits of P_j[0].  exp(seg_d) = q_{j-d} * q_j with q = exp(em/2),
//   so the inner loop has NO transcendental ops at all.
// ---------------------------------------------------------------------------
__global__ __launch_bounds__(192, 1) void semicrf_main_kernel(
    const float* __restrict__ em, const int* __restrict__ tags,
    const int* __restrict__ lens, const float* __restrict__ start_t,
    const float* __restrict__ end_t, const float* __restrict__ trans)
{
    const int b   = blockIdx.x;
    const int tid = threadIdx.x;
    const int t   = tid >> 2;    // tag 0..47
    const int c   = tid & 3;     // dot-product / ring-term slice 0..3

    __shared__ __align__(16) float p_sh[2][48];  // P_{j-1}, P_j
    __shared__ float q_ring[16][49];             // q rows j-7 .. j+1
    __shared__ float r_ring[8][49];              // r-hat rows j-8 .. j-1
    __shared__ int   K_ring[16];                 // C shifts (ints)
    __shared__ float fin[48];

    // exp(trans[t', t]) for t' = 12c .. 12c+11
    float e12[12];
#pragma unroll
    for (int k = 0; k < 12; ++k)
        e12[k] = __expf(trans[(12 * c + k) * Tc + t]);

    const float st_t  = start_t[t];
    const float em0t  = em[(0 * Bc + b) * Tc + t];
    const float estq0 = __expf(st_t + 0.5f * em0t);   // exp(start)*q_0

    float emA = 0.f, emB = 0.f;   // prefetched emission rows j+2, j+3
    if (c == 0) {
        const float e1 = em[(1 * Bc + b) * Tc + t];
        emA = em[(2 * Bc + b) * Tc + t];
        emB = em[(3 * Bc + b) * Tc + t];
        q_ring[0][t] = __expf(0.5f * em0t);
        q_ring[1][t] = __expf(0.5f * e1);
        p_sh[0][t]   = __expf(st_t + em0t);           // P_0, scale C_{-1}=0
    }
    if (tid < 16) K_ring[tid] = 0;
    __syncthreads();
    if (tid == 0) {                                   // C_0
        K_ring[0] = ((__float_as_int(p_sh[0][0]) >> 23) & 0xff) - 127;
    }
    __syncthreads();

    for (int j = 1; j < Lc; ++j) {
        const int Cjm1 = K_ring[(j - 1) & 15];        // C_{j-1}
        const int Cjm2 = K_ring[(j - 2) & 15];        // C_{j-2}

        // partial dot: pp_c = sum over 12 t' of P_{j-1}[t'] * etrans[t',t]
        const float* pv = p_sh[(j - 1) & 1];
        const float4 pA = *(const float4*)(pv + 12 * c);
        const float4 pB = *(const float4*)(pv + 12 * c + 4);
        const float4 pC = *(const float4*)(pv + 12 * c + 8);
        float s0 = pA.x * e12[0];
        float s1 = pA.y * e12[1];
        float s2 = pA.z * e12[2];
        float s3 = pA.w * e12[3];
        s0 = fmaf(pB.x, e12[4], s0);
        s1 = fmaf(pB.y, e12[5], s1);
        s2 = fmaf(pB.z, e12[6], s2);
        s3 = fmaf(pB.w, e12[7], s3);
        s0 = fmaf(pC.x, e12[8],  s0);
        s1 = fmaf(pC.y, e12[9],  s1);
        s2 = fmaf(pC.z, e12[10], s2);
        s3 = fmaf(pC.w, e12[11], s3);
        const float pp = (s0 + s1) + (s2 + s3);

        const float qj = q_ring[j & 15][t];

        // d = 0 contribution (per-lane share of it)
        float y = pp * (pow2i(Cjm2 - Cjm1) * qj);

        // ring terms: this lane owns d = c+1 and d = c+5
        {
            const int dd = c + 1;
            const int m  = j - 1 - dd;
            if (m >= 0) {
                const float w = pow2i(K_ring[(m - 1) & 15] - Cjm1);
                y = fmaf(r_ring[m & 7][t] * q_ring[(j - dd) & 15][t], w, y);
            } else if (dd == j) {
                y = fmaf(estq0, pow2i(-Cjm1), y);
            }
        }
        if (c < 3) {
            const int dd = c + 5;
            const int m  = j - 1 - dd;
            if (m >= 0) {
                const float w = pow2i(K_ring[(m - 1) & 15] - Cjm1);
                y = fmaf(r_ring[m & 7][t] * q_ring[(j - dd) & 15][t], w, y);
            } else if (dd == j) {
                y = fmaf(estq0, pow2i(-Cjm1), y);
            }
        }

        // 4-lane butterfly: s (alpha, sans qj) and rr (= r-hat_{j-1}[t])
        float s = y, rr = pp;
        s  += __shfl_xor_sync(0xffffffffu, s, 1);
        rr += __shfl_xor_sync(0xffffffffu, rr, 1);
        s  += __shfl_xor_sync(0xffffffffu, s, 2);
        rr += __shfl_xor_sync(0xffffffffu, rr, 2);
        const float Pj = qj * s;

        if (c == 0) {
            p_sh[j & 1][t]         = Pj;
            r_ring[(j - 1) & 7][t] = rr;
            // q pipeline: row j+1 ready for next step; refill prefetch regs
            q_ring[(j + 1) & 15][t] = __expf(0.5f * emA);
            emA = emB;
            int nr = j + 3; if (nr > Lc - 1) nr = Lc - 1;
            emB = em[(nr * Bc + b) * Tc + t];
        }
        if (tid == 0) {
            K_ring[j & 15] = Cjm1 + (((__float_as_int(Pj) >> 23) & 0xff) - 127);
        }
        __syncthreads();
    }

    // denominator: C_510*ln2 + log( sum_t P_511[t] * exp(end_t[t]) )
    if (c == 0) fin[t] = p_sh[(Lc - 1) & 1][t] * __expf(end_t[t]);
    __syncthreads();
    float den = 0.f;
    if (tid == 0) {
        float sum = 0.f;
        for (int i = 0; i < Tc; ++i) sum += fin[i];
        den = (float)K_ring[(Lc - 2) & 15] * 0.6931471805599453f + logf(sum);
    }

    // ---- numerator (warp 0 only) ----
    if (tid < 32) {
        const int lane = tid;
        // inclusive prefix sums of lens over the 64 segments
        int c1 = lens[lane * Bc + b];
#pragma unroll
        for (int o = 1; o < 32; o <<= 1) {
            int n = __shfl_up_sync(0xffffffffu, c1, o);
            if (lane >= o) c1 += n;
        }
        const int tot1 = __shfl_sync(0xffffffffu, c1, 31);
        int c2 = (lane + 32 < 64) ? lens[(lane + 32) * Bc + b] : 0;
#pragma unroll
        for (int o = 1; o < 32; o <<= 1) {
            int n = __shfl_up_sync(0xffffffffu, c2, o);
            if (lane >= o) c2 += n;
        }
        c2 += tot1;

        float acc = 0.f;
        {   // segment s = lane (0..31)
            int st = c1; if (st > Lc - 1) st = Lc - 1;
            const int en = st + lens[(lane + 1) * Bc + b];
            const int tg = tags[st * Bc + b];
            const float seg = 0.5f * (em[(st * Bc + b) * Tc + tg] +
                                      em[((en - 1) * Bc + b) * Tc + tg]);
            acc += seg + trans[tags[(st - 1) * Bc + b] * Tc +
                               tags[(en - 1) * Bc + b]];
        }
        if (lane + 32 < 63) {   // segment s = lane+32 (32..62)
            int st = c2; if (st > Lc - 1) st = Lc - 1;
            const int en = st + lens[(lane + 33) * Bc + b];
            const int tg = tags[st * Bc + b];
            const float seg = 0.5f * (em[(st * Bc + b) * Tc + tg] +
                                      em[((en - 1) * Bc + b) * Tc + tg]);
            acc += seg + trans[tags[(st - 1) * Bc + b] * Tc +
                               tags[(en - 1) * Bc + b]];
        }
#pragma unroll
        for (int o = 16; o; o >>= 1) acc += __shfl_xor_sync(0xffffffffu, acc, o);

        if (lane == 0) {
            const int t0 = tags[b];
            const int l0 = lens[b];
            float sc = start_t[t0];
            sc += 0.5f * (em[(0 * Bc + b) * Tc + t0] +
                          em[((l0 - 1) * Bc + b) * Tc + t0]);
            sc += end_t[tags[(Lc - 1) * Bc + b]];
            g_llh[b] = sc + acc - den;
        }
    }
}

// ---------------------------------------------------------------------------
// Final: sum the 32 per-batch llh values (fixed tree -> deterministic).
// ---------------------------------------------------------------------------
__global__ void semicrf_final_kernel(float* __restrict__ out)
{
    float v = g_llh[threadIdx.x];
#pragma unroll
    for (int o = 16; o; o >>= 1) v += __shfl_xor_sync(0xffffffffu, v, o);
    if (threadIdx.x == 0) out[0] = v;
}

extern "C" void kernel_launch(void* const* d_in, const int* in_sizes, int n_in,
                              void* d_out, int out_size) {
    const float* emissions = (const float*)d_in[0];
    const int*   tags      = (const int*)d_in[1];
    const int*   lens      = (const int*)d_in[2];
    // d_in[3] = mask (all ones by construction; unused)
    const float* start_t   = (const float*)d_in[4];
    const float* end_t     = (const float*)d_in[5];
    const float* trans     = (const float*)d_in[6];
    float* out = (float*)d_out;

    semicrf_main_kernel<<<Bc, 192>>>(emissions, tags, lens, start_t, end_t, trans);
    semicrf_final_kernel<<<1, 32>>>(out);
}

// round 3
// speedup vs baseline: 1.0654x; 1.0654x over previous
#include <cuda_runtime.h>

#define Lc 512
#define Bc 32
#define Tc 48

__device__ float g_llh[Bc];
__device__ int   g_cnt = 0;

// 2^e as float; e <= -127 -> 0 (negligible), e in [-126,127] exact.
__device__ __forceinline__ float pow2i(int e) {
    e = (e < -127) ? -127 : e;
    return __int_as_float((e + 127) << 23);
}

// ---------------------------------------------------------------------------
// One block per batch; 192 threads = (t=48) x (c=4).
// Scaled-linear semi-CRF forward:
//   hatP_j[t] = exp(alpha_j[t]) * 2^{-G_j},  G tracked with a 2-step lag so
//   the scale update is NEVER on the inter-barrier critical path.
//   exp(seg_d) = q_{j-d} * q_j with q = exp(em/2): no transcendentals in loop.
// ---------------------------------------------------------------------------
__global__ __launch_bounds__(192, 1) void semicrf_main_kernel(
    const float* __restrict__ em, const int* __restrict__ tags,
    const int* __restrict__ lens, const float* __restrict__ start_t,
    const float* __restrict__ end_t, const float* __restrict__ trans,
    float* __restrict__ out)
{
    const int b   = blockIdx.x;
    const int tid = threadIdx.x;
    const int t   = tid >> 2;    // tag 0..47
    const int c   = tid & 3;     // slice 0..3
    const int dd1 = c + 1;       // ring term 1 (d = 1..4)
    const int dd2 = c + 5;       // ring term 2 (d = 5..7, c<3 only)

    __shared__ __align__(16) float p_sh[2][48];  // hatP_{j-1}, hatP_j
    __shared__ float q_ring[16][49];             // q rows
    __shared__ float r_ring[8][49];              // r rows j-8 .. j-1
    __shared__ int   K_sh[16];                   // G shifts
    __shared__ float fin[48];
    __shared__ int   isLast;

    // exp(trans[t', t]) for t' = 12c .. 12c+11
    float e12[12];
#pragma unroll
    for (int k = 0; k < 12; ++k)
        e12[k] = __expf(trans[(12 * c + k) * Tc + t]);

    const float st_t  = start_t[t];
    const float em0t  = em[(0 * Bc + b) * Tc + t];
    const float estq0 = __expf(st_t + 0.5f * em0t);   // exp(start)*q_0

    float qnext = 0.f, emA = 0.f, emB = 0.f, emC = 0.f;
    if (c == 0) p_sh[0][t] = __expf(st_t + em0t);     // hatP_0, G_0 = 0
    if (c == 3) {
        q_ring[0][t] = __expf(0.5f * em0t);
        q_ring[1][t] = __expf(0.5f * em[(1 * Bc + b) * Tc + t]);
        qnext = __expf(0.5f * em[(2 * Bc + b) * Tc + t]);   // q row 2
        emA = em[(3 * Bc + b) * Tc + t];
        emB = em[(4 * Bc + b) * Tc + t];
        emC = em[(5 * Bc + b) * Tc + t];
    }
    if (tid < 16) K_sh[tid] = 0;
    int   Greg  = 0;                                   // tid0: G_j
    float stash = (tid == 0) ? __expf(st_t + em0t) : 0.f;  // tid0: hatP_{j-1}[0]
    __syncthreads();

    for (int j = 1; j < Lc; ++j) {
        // tid0: scale update, pure register state -> fully off-chain.
        // Writes slot (j+1)&15; readers touch slots (j-8..j)&15: disjoint.
        if (tid == 0) {
            const int e = ((__float_as_int(stash) >> 23) & 0xff) - 127;
            Greg += e;                       // G_{j+1} = G_j + e_{j-1}
            K_sh[(j + 1) & 15] = Greg;
        }

        const int Gj   = K_sh[j & 15];
        const int Gjm1 = K_sh[(j - 1) & 15];

        // partial dot: pp = sum over 12 t' of hatP_{j-1}[t'] * etrans[t',t]
        const float* pv = p_sh[(j - 1) & 1] + 12 * c;
        const float4 pA = *(const float4*)(pv);
        const float4 pB = *(const float4*)(pv + 4);
        const float4 pC = *(const float4*)(pv + 8);
        float s0 = pA.x * e12[0];
        float s1 = pA.y * e12[1];
        float s2 = pA.z * e12[2];
        float s3 = pA.w * e12[3];
        s0 = fmaf(pB.x, e12[4], s0);
        s1 = fmaf(pB.y, e12[5], s1);
        s2 = fmaf(pB.z, e12[6], s2);
        s3 = fmaf(pB.w, e12[7], s3);
        s0 = fmaf(pC.x, e12[8],  s0);
        s1 = fmaf(pC.y, e12[9],  s1);
        s2 = fmaf(pC.z, e12[10], s2);
        s3 = fmaf(pC.w, e12[11], s3);
        const float pp = (s0 + s1) + (s2 + s3);

        const float qj = q_ring[j & 15][t];

        // d = 0 term (lane share)
        float y = pp * (pow2i(Gjm1 - Gj) * qj);

        // ring terms: weight 2^{G_m - G_j}, m = j-1-d
        {
            const int m = j - 1 - dd1;
            if (m >= 0) {
                y = fmaf(r_ring[m & 7][t] * q_ring[(j - dd1) & 15][t],
                         pow2i(K_sh[m & 15] - Gj), y);
            } else if (dd1 == j) {
                y = fmaf(estq0, pow2i(-Gj), y);
            }
        }
        if (c < 3) {
            const int m = j - 1 - dd2;
            if (m >= 0) {
                y = fmaf(r_ring[m & 7][t] * q_ring[(j - dd2) & 15][t],
                         pow2i(K_sh[m & 15] - Gj), y);
            } else if (dd2 == j) {
                y = fmaf(estq0, pow2i(-Gj), y);
            }
        }

        // 4-lane butterfly: s (alpha sans qj) and rr (= r_{j-1}[t])
        float s = y, rr = pp;
        s  += __shfl_xor_sync(0xffffffffu, s, 1);
        rr += __shfl_xor_sync(0xffffffffu, rr, 1);
        s  += __shfl_xor_sync(0xffffffffu, s, 2);
        rr += __shfl_xor_sync(0xffffffffu, rr, 2);

        // distributed epilogue: one STS per lane, all in parallel
        if (c == 1) p_sh[j & 1][t] = qj * s;
        if (c == 2) r_ring[(j - 1) & 7][t] = rr;
        if (c == 3) {
            q_ring[(j + 1) & 15][t] = qnext;           // q row j+1 (precomputed)
            qnext = __expf(0.5f * emA);                // q row j+2 for next step
            emA = emB; emB = emC;
            int nr = j + 6; if (nr > Lc - 1) nr = Lc - 1;
            emC = em[(nr * Bc + b) * Tc + t];
        }
        if (tid == 0) stash = qj * s;                  // hatP_j[0]
        __syncthreads();
    }

    // denominator: G_511*ln2 + log( sum_t hatP_511[t] * exp(end_t[t]) )
    if (c == 0) fin[t] = p_sh[(Lc - 1) & 1][t] * __expf(end_t[t]);
    __syncthreads();
    float den = 0.f;
    if (tid == 0) {
        float sum = 0.f;
        for (int i = 0; i < Tc; ++i) sum += fin[i];
        den = (float)K_sh[(Lc - 1) & 15] * 0.6931471805599453f + logf(sum);
    }

    // ---- numerator (warp 0 only) ----
    if (tid < 32) {
        const int lane = tid;
        int c1 = lens[lane * Bc + b];
#pragma unroll
        for (int o = 1; o < 32; o <<= 1) {
            int n = __shfl_up_sync(0xffffffffu, c1, o);
            if (lane >= o) c1 += n;
        }
        const int tot1 = __shfl_sync(0xffffffffu, c1, 31);
        int c2 = (lane + 32 < 64) ? lens[(lane + 32) * Bc + b] : 0;
#pragma unroll
        for (int o = 1; o < 32; o <<= 1) {
            int n = __shfl_up_sync(0xffffffffu, c2, o);
            if (lane >= o) c2 += n;
        }
        c2 += tot1;

        float acc = 0.f;
        {   // segment s = lane (0..31)
            int st = c1; if (st > Lc - 1) st = Lc - 1;
            const int en = st + lens[(lane + 1) * Bc + b];
            const int tg = tags[st * Bc + b];
            const float seg = 0.5f * (em[(st * Bc + b) * Tc + tg] +
                                      em[((en - 1) * Bc + b) * Tc + tg]);
            acc += seg + trans[tags[(st - 1) * Bc + b] * Tc +
                               tags[(en - 1) * Bc + b]];
        }
        if (lane + 32 < 63) {   // segment s = lane+32 (32..62)
            int st = c2; if (st > Lc - 1) st = Lc - 1;
            const int en = st + lens[(lane + 33) * Bc + b];
            const int tg = tags[st * Bc + b];
            const float seg = 0.5f * (em[(st * Bc + b) * Tc + tg] +
                                      em[((en - 1) * Bc + b) * Tc + tg]);
            acc += seg + trans[tags[(st - 1) * Bc + b] * Tc +
                               tags[(en - 1) * Bc + b]];
        }
#pragma unroll
        for (int o = 16; o; o >>= 1) acc += __shfl_xor_sync(0xffffffffu, acc, o);

        if (lane == 0) {
            const int t0 = tags[b];
            const int l0 = lens[b];
            float sc = start_t[t0];
            sc += 0.5f * (em[(0 * Bc + b) * Tc + t0] +
                          em[((l0 - 1) * Bc + b) * Tc + t0]);
            sc += end_t[tags[(Lc - 1) * Bc + b]];
            g_llh[b] = sc + acc - den;
        }
    }

    // ---- last-block final reduction (single kernel, fixed order) ----
    __threadfence();
    if (tid == 0) isLast = (atomicAdd(&g_cnt, 1) == Bc - 1);
    __syncthreads();
    if (isLast) {
        if (tid == 0) __threadfence();
        __syncthreads();
        if (tid < 32) {
            float v = *((volatile float*)&g_llh[tid]);
#pragma unroll
            for (int o = 16; o; o >>= 1) v += __shfl_xor_sync(0xffffffffu, v, o);
            if (tid == 0) { out[0] = v; g_cnt = 0; }
        }
    }
}

extern "C" void kernel_launch(void* const* d_in, const int* in_sizes, int n_in,
                              void* d_out, int out_size) {
    const float* emissions = (const float*)d_in[0];
    const int*   tags      = (const int*)d_in[1];
    const int*   lens      = (const int*)d_in[2];
    // d_in[3] = mask (all ones by construction; unused)
    const float* start_t   = (const float*)d_in[4];
    const float* end_t     = (const float*)d_in[5];
    const float* trans     = (const float*)d_in[6];
    float* out = (float*)d_out;

    semicrf_main_kernel<<<Bc, 192>>>(emissions, tags, lens, start_t, end_t,
                                     trans, out);
}

// round 4
// speedup vs baseline: 3.0563x; 2.8688x over previous
#include <cuda_runtime.h>

#define Lc 512
#define Bc 32
#define Tc 48
typedef unsigned long long u64;

__device__ float g_llh[Bc];
__device__ int   g_cnt = 0;

__device__ __forceinline__ u64 pk2(float x, float y) {
    u64 r; asm("mov.b64 %0,{%1,%2};" : "=l"(r) : "f"(x), "f"(y)); return r;
}
__device__ __forceinline__ void upk(u64 v, float& x, float& y) {
    asm("mov.b64 {%0,%1},%2;" : "=f"(x), "=f"(y) : "l"(v));
}
__device__ __forceinline__ u64 fma2(u64 a, u64 b, u64 c) {
    u64 d; asm("fma.rn.f32x2 %0,%1,%2,%3;" : "=l"(d) : "l"(a), "l"(b), "l"(c)); return d;
}
__device__ __forceinline__ u64 mul2(u64 a, u64 b) {
    u64 d; asm("mul.rn.f32x2 %0,%1,%2;" : "=l"(d) : "l"(a), "l"(b)); return d;
}
__device__ __forceinline__ u64 add2(u64 a, u64 b) {
    u64 d; asm("add.rn.f32x2 %0,%1,%2;" : "=l"(d) : "l"(a), "l"(b)); return d;
}
__device__ __forceinline__ float pow2i(int e) {
    e = (e < -127) ? -127 : e;
    return __int_as_float((e + 127) << 23);
}

// One step of the scaled-linear recursion. U_ must be a compile-time constant
// (ring indices fold to named registers); J_ may be runtime (address math only).
#define STEP(J_, U_, HS_) {                                                    \
    /* exponent shift from hatP_{j-1}[0] (broadcast LDS) */                    \
    const float p0_ = Pshf[((U_) & 1) ^ 1][0];                                 \
    const int   e_  = ((__float_as_int(p0_) >> 23) & 255) - 127;               \
    G += e_;                                                                   \
    const float sc_ = pow2i(-e_);                                              \
    const u64  sc2_ = pk2(sc_, sc_);                                           \
    qring[(U_) & 7] = qtmp;                      /* insert q_j */              \
    /* matvec: pp[t] = sum_t' hatP_{j-1}[t'] * etrans[t',t], packed over t' */ \
    const ulonglong2* PV_ = (const ulonglong2*)&Pshf[((U_) & 1) ^ 1][0];       \
    u64 A_[4] = {0, 0, 0, 0}, B_[4] = {0, 0, 0, 0};                            \
    _Pragma("unroll") for (int i_ = 0; i_ < 12; ++i_) {                        \
        const ulonglong2 pv_ = PV_[i_];                                        \
        A_[(2 * i_) & 3]     = fma2(pv_.x, Ea[2 * i_],     A_[(2 * i_) & 3]);  \
        A_[(2 * i_ + 1) & 3] = fma2(pv_.y, Ea[2 * i_ + 1], A_[(2 * i_ + 1) & 3]); \
        B_[(2 * i_) & 3]     = fma2(pv_.x, Eb[2 * i_],     B_[(2 * i_) & 3]);  \
        B_[(2 * i_ + 1) & 3] = fma2(pv_.y, Eb[2 * i_ + 1], B_[(2 * i_ + 1) & 3]); \
    }                                                                          \
    float ax_, ay_, bx_, by_;                                                  \
    upk(add2(add2(A_[0], A_[1]), add2(A_[2], A_[3])), ax_, ay_);               \
    upk(add2(add2(B_[0], B_[1]), add2(B_[2], B_[3])), bx_, by_);               \
    const u64 rn_ = mul2(pk2(ax_ + ay_, bx_ + by_), sc2_);  /* r_{j-1} */      \
    u64 Uacc_ = mul2(rn_, qring[(U_) & 7]);                 /* d = 0 */        \
    _Pragma("unroll") for (int d_ = 1; d_ < 8; ++d_) {                         \
        const int rs_ = ((U_) - 1 - d_) & 7, qs_ = ((U_) - d_) & 7;            \
        rring[rs_] = mul2(rring[rs_], sc2_);                                   \
        Uacc_ = fma2(rring[rs_], qring[qs_], Uacc_);                           \
    }                                                                          \
    if (HS_) { s2 = mul2(s2, sc2_); Uacc_ = add2(Uacc_, s2); }                 \
    rring[((U_) - 1) & 7] = rn_;                                               \
    P2last = mul2(qring[(U_) & 7], Uacc_);                  /* hatP_j */       \
    if (lane < 24) {                                                           \
        float px_, py_; upk(P2last, px_, py_);                                 \
        *(float2*)&Pshf[(U_) & 1][2 * lc] = make_float2(px_, py_);             \
    }                                                                          \
    /* q pipeline: q_{j+1} from prefetched row; refill prefetch (row j+4) */   \
    qtmp = pk2(__expf(0.5f * pfA.x), __expf(0.5f * pfA.y));                    \
    pfA = pfB; pfB = pfC;                                                      \
    { int nr_ = (J_) + 4; if (nr_ > Lc - 1) nr_ = Lc - 1;                      \
      pfC = *((const float2*)(em + (size_t)(nr_ * Bc + b) * Tc) + lc); }       \
    __syncwarp();                                                              \
}

// ---------------------------------------------------------------------------
// One WARP per batch. Tags packed 2/lane (lane l -> tags 2l, 2l+1; lanes
// 24-31 duplicate lane 23's work harmlessly). No __syncthreads anywhere.
// ---------------------------------------------------------------------------
__global__ __launch_bounds__(32, 1) void semicrf_main_kernel(
    const float* __restrict__ em, const int* __restrict__ tags,
    const int* __restrict__ lens, const float* __restrict__ start_t,
    const float* __restrict__ end_t, const float* __restrict__ trans)
{
    const int b    = blockIdx.x;
    const int lane = threadIdx.x;
    const int lc   = (lane < 24) ? lane : 23;
    const int t0   = 2 * lc, t1 = 2 * lc + 1;

    __shared__ __align__(16) float Pshf[2][48];

    // exp(trans) columns for this lane's two tags, packed over t' pairs.
    u64 Ea[24], Eb[24];
#pragma unroll
    for (int i = 0; i < 24; ++i) {
        Ea[i] = pk2(__expf(trans[(2 * i) * Tc + t0]),
                    __expf(trans[(2 * i + 1) * Tc + t0]));
        Eb[i] = pk2(__expf(trans[(2 * i) * Tc + t1]),
                    __expf(trans[(2 * i + 1) * Tc + t1]));
    }

    const float st0 = start_t[t0], st1 = start_t[t1];
    const float2 e0v = *((const float2*)(em + (size_t)(0 * Bc + b) * Tc) + lc);
    const float2 e1v = *((const float2*)(em + (size_t)(1 * Bc + b) * Tc) + lc);
    float2 pfA = *((const float2*)(em + (size_t)(2 * Bc + b) * Tc) + lc);
    float2 pfB = *((const float2*)(em + (size_t)(3 * Bc + b) * Tc) + lc);
    float2 pfC = *((const float2*)(em + (size_t)(4 * Bc + b) * Tc) + lc);

    u64 qring[8], rring[8];
#pragma unroll
    for (int i = 0; i < 8; ++i) rring[i] = 0;
    qring[0] = pk2(__expf(0.5f * e0v.x), __expf(0.5f * e0v.y));
    u64 qtmp = pk2(__expf(0.5f * e1v.x), __expf(0.5f * e1v.y));   // q_1
    u64 s2   = pk2(__expf(st0 + 0.5f * e0v.x),
                   __expf(st1 + 0.5f * e0v.y));                    // exp(st)*q_0
    u64 P2last = mul2(s2, qring[0]);                               // hatP_0
    if (lane < 24) {
        float px, py; upk(P2last, px, py);
        *(float2*)&Pshf[0][2 * lc] = make_float2(px, py);
    }
    int G = 0;
    __syncwarp();

    // prologue j = 1..7 (start-segment terms active; fully unrolled)
#pragma unroll
    for (int j = 1; j < 8; ++j) { STEP(j, j, true) }

    // main loop j = 8..511, unrolled x8 (ring indices constant)
    for (int jb = 8; jb < Lc; jb += 8) {
#pragma unroll
        for (int u = 0; u < 8; ++u) { STEP(jb + u, u, false) }
    }

    // denominator: G*ln2 + log( sum_t hatP_511[t] * exp(end_t[t]) )
    float dv = 0.f;
    if (lane < 24) {
        float px, py; upk(P2last, px, py);
        dv = px * __expf(end_t[t0]) + py * __expf(end_t[t1]);
    }
#pragma unroll
    for (int o = 16; o; o >>= 1) dv += __shfl_xor_sync(0xffffffffu, dv, o);
    const float den = (float)G * 0.6931471805599453f + logf(dv);

    // ---- numerator (this warp) ----
    int c1 = lens[lane * Bc + b];
#pragma unroll
    for (int o = 1; o < 32; o <<= 1) {
        int n = __shfl_up_sync(0xffffffffu, c1, o);
        if (lane >= o) c1 += n;
    }
    const int tot1 = __shfl_sync(0xffffffffu, c1, 31);
    int c2 = (lane + 32 < 64) ? lens[(lane + 32) * Bc + b] : 0;
#pragma unroll
    for (int o = 1; o < 32; o <<= 1) {
        int n = __shfl_up_sync(0xffffffffu, c2, o);
        if (lane >= o) c2 += n;
    }
    c2 += tot1;

    float acc = 0.f;
    {   // segment s = lane (0..31)
        int st = c1; if (st > Lc - 1) st = Lc - 1;
        const int en = st + lens[(lane + 1) * Bc + b];
        const int tg = tags[st * Bc + b];
        const float seg = 0.5f * (em[(st * Bc + b) * Tc + tg] +
                                  em[((en - 1) * Bc + b) * Tc + tg]);
        acc += seg + trans[tags[(st - 1) * Bc + b] * Tc +
                           tags[(en - 1) * Bc + b]];
    }
    if (lane + 32 < 63) {   // segment s = lane+32 (32..62)
        int st = c2; if (st > Lc - 1) st = Lc - 1;
        const int en = st + lens[(lane + 33) * Bc + b];
        const int tg = tags[st * Bc + b];
        const float seg = 0.5f * (em[(st * Bc + b) * Tc + tg] +
                                  em[((en - 1) * Bc + b) * Tc + tg]);
        acc += seg + trans[tags[(st - 1) * Bc + b] * Tc +
                           tags[(en - 1) * Bc + b]];
    }
#pragma unroll
    for (int o = 16; o; o >>= 1) acc += __shfl_xor_sync(0xffffffffu, acc, o);

    if (lane == 0) {
        const int tg0 = tags[b];
        const int l0  = lens[b];
        float sc = start_t[tg0];
        sc += 0.5f * (em[(0 * Bc + b) * Tc + tg0] +
                      em[((l0 - 1) * Bc + b) * Tc + tg0]);
        sc += end_t[tags[(Lc - 1) * Bc + b]];
        g_llh[b] = sc + acc - den;
    }
}

// ---------------------------------------------------------------------------
// Final: sum the 32 per-batch llh values (fixed tree -> deterministic).
// ---------------------------------------------------------------------------
__global__ void semicrf_final_kernel(float* __restrict__ out)
{
    float v = g_llh[threadIdx.x];
#pragma unroll
    for (int o = 16; o; o >>= 1) v += __shfl_xor_sync(0xffffffffu, v, o);
    if (threadIdx.x == 0) out[0] = v;
}

extern "C" void kernel_launch(void* const* d_in, const int* in_sizes, int n_in,
                              void* d_out, int out_size) {
    const float* emissions = (const float*)d_in[0];
    const int*   tags      = (const int*)d_in[1];
    const int*   lens      = (const int*)d_in[2];
    // d_in[3] = mask (all ones by construction; unused)
    const float* start_t   = (const float*)d_in[4];
    const float* end_t     = (const float*)d_in[5];
    const float* trans     = (const float*)d_in[6];
    float* out = (float*)d_out;

    semicrf_main_kernel<<<Bc, 32>>>(emissions, tags, lens, start_t, end_t, trans);
    semicrf_final_kernel<<<1, 32>>>(out);
}

// round 5
// speedup vs baseline: 3.1355x; 1.0259x over previous
#include <cuda_runtime.h>

#define Lc 512
#define Bc 32
#define Tc 48
typedef unsigned long long u64;

__device__ float g_llh[Bc];
__device__ int   g_cnt = 0;

__device__ __forceinline__ u64 pk2(float x, float y) {
    u64 r; asm("mov.b64 %0,{%1,%2};" : "=l"(r) : "f"(x), "f"(y)); return r;
}
__device__ __forceinline__ void upk(u64 v, float& x, float& y) {
    asm("mov.b64 {%0,%1},%2;" : "=f"(x), "=f"(y) : "l"(v));
}
__device__ __forceinline__ u64 fma2(u64 a, u64 b, u64 c) {
    u64 d; asm("fma.rn.f32x2 %0,%1,%2,%3;" : "=l"(d) : "l"(a), "l"(b), "l"(c)); return d;
}
__device__ __forceinline__ u64 mul2(u64 a, u64 b) {
    u64 d; asm("mul.rn.f32x2 %0,%1,%2;" : "=l"(d) : "l"(a), "l"(b)); return d;
}
__device__ __forceinline__ u64 add2(u64 a, u64 b) {
    u64 d; asm("add.rn.f32x2 %0,%1,%2;" : "=l"(d) : "l"(a), "l"(b)); return d;
}
__device__ __forceinline__ float pow2i(int e) {
    e = (e < -127) ? -127 : e;
    return __int_as_float((e + 127) << 23);
}

// One recursion step. U_ compile-time (ring indices fold to registers).
// RS_: rescale state this step (every 4th step; every step in prologue).
// HS_: start-segment term active (prologue only; HS_ implies RS_).
#define STEP(J_, U_, RS_, HS_) {                                               \
    qring[(U_) & 7] = qtmp;                      /* insert q_j */              \
    int e_ = 0; u64 sc2_ = 0;                                                  \
    if (RS_) {                                                                 \
        const float p0_ = Pshf[((U_) & 1) ^ 1][0];                             \
        e_ = ((__float_as_int(p0_) >> 23) & 255) - 127;                        \
        G += e_;                                                               \
        const float sc_ = pow2i(-e_);                                          \
        sc2_ = pk2(sc_, sc_);                                                  \
    }                                                                          \
    /* matvec: pp[t] = sum_t' hatP_{j-1}[t'] * etrans[t',t], packed over t' */ \
    const ulonglong2* PV_ = (const ulonglong2*)&Pshf[((U_) & 1) ^ 1][0];       \
    u64 A_[4] = {0, 0, 0, 0}, B_[4] = {0, 0, 0, 0};                            \
    _Pragma("unroll") for (int i_ = 0; i_ < 12; ++i_) {                        \
        const ulonglong2 pv_ = PV_[i_];                                        \
        A_[(2 * i_) & 3]     = fma2(pv_.x, Ea[2 * i_],     A_[(2 * i_) & 3]);  \
        A_[(2 * i_ + 1) & 3] = fma2(pv_.y, Ea[2 * i_ + 1], A_[(2 * i_ + 1) & 3]); \
        B_[(2 * i_) & 3]     = fma2(pv_.x, Eb[2 * i_],     B_[(2 * i_) & 3]);  \
        B_[(2 * i_ + 1) & 3] = fma2(pv_.y, Eb[2 * i_ + 1], B_[(2 * i_ + 1) & 3]); \
    }                                                                          \
    float ax_, ay_, bx_, by_;                                                  \
    upk(add2(add2(A_[0], A_[1]), add2(A_[2], A_[3])), ax_, ay_);               \
    upk(add2(add2(B_[0], B_[1]), add2(B_[2], B_[3])), bx_, by_);               \
    u64 rn_ = pk2(ax_ + ay_, bx_ + by_);                    /* r_{j-1} */      \
    if (RS_) rn_ = mul2(rn_, sc2_);                                            \
    u64 Uacc_ = mul2(rn_, qring[(U_) & 7]);                 /* d = 0 */        \
    _Pragma("unroll") for (int d_ = 1; d_ < 8; ++d_) {                         \
        const int rs_ = ((U_) - 1 - d_) & 7, qs_ = ((U_) - d_) & 7;            \
        if (RS_) rring[rs_] = mul2(rring[rs_], sc2_);                          \
        Uacc_ = fma2(rring[rs_], qring[qs_], Uacc_);                           \
    }                                                                          \
    if (HS_) { s2 = mul2(s2, sc2_); Uacc_ = add2(Uacc_, s2); }                 \
    rring[((U_) - 1) & 7] = rn_;                                               \
    P2last = mul2(qring[(U_) & 7], Uacc_);                  /* hatP_j */       \
    if (lane < 24) {                                                           \
        float px_, py_; upk(P2last, px_, py_);                                 \
        *(float2*)&Pshf[(U_) & 1][2 * lc] = make_float2(px_, py_);             \
    }                                                                          \
    /* q pipeline: q_{j+1}; refill prefetch (row j+4) */                       \
    qtmp = pk2(__expf(0.5f * pfA.x), __expf(0.5f * pfA.y));                    \
    pfA = pfB; pfB = pfC;                                                      \
    { int nr_ = (J_) + 4; if (nr_ > Lc - 1) nr_ = Lc - 1;                      \
      pfC = *((const float2*)(em + (size_t)(nr_ * Bc + b) * Tc) + lc); }       \
    __syncwarp();                                                              \
}

// ---------------------------------------------------------------------------
// One WARP per batch; lane l -> tags 2l, 2l+1 (lanes 24-31 shadow lane 23).
// No __syncthreads on the recursion. State rescaled every 4 steps only.
// ---------------------------------------------------------------------------
__global__ __launch_bounds__(32, 1) void semicrf_main_kernel(
    const float* __restrict__ em, const int* __restrict__ tags,
    const int* __restrict__ lens, const float* __restrict__ start_t,
    const float* __restrict__ end_t, const float* __restrict__ trans,
    float* __restrict__ out)
{
    const int b    = blockIdx.x;
    const int lane = threadIdx.x;
    const int lc   = (lane < 24) ? lane : 23;
    const int t0   = 2 * lc, t1 = 2 * lc + 1;

    __shared__ __align__(16) float Pshf[2][48];
    __shared__ int isLast;

    // exp(trans) columns for this lane's two tags, packed over t' pairs.
    u64 Ea[24], Eb[24];
#pragma unroll
    for (int i = 0; i < 24; ++i) {
        Ea[i] = pk2(__expf(trans[(2 * i) * Tc + t0]),
                    __expf(trans[(2 * i + 1) * Tc + t0]));
        Eb[i] = pk2(__expf(trans[(2 * i) * Tc + t1]),
                    __expf(trans[(2 * i + 1) * Tc + t1]));
    }

    const float st0 = start_t[t0], st1 = start_t[t1];
    const float2 e0v = *((const float2*)(em + (size_t)(0 * Bc + b) * Tc) + lc);
    const float2 e1v = *((const float2*)(em + (size_t)(1 * Bc + b) * Tc) + lc);
    float2 pfA = *((const float2*)(em + (size_t)(2 * Bc + b) * Tc) + lc);
    float2 pfB = *((const float2*)(em + (size_t)(3 * Bc + b) * Tc) + lc);
    float2 pfC = *((const float2*)(em + (size_t)(4 * Bc + b) * Tc) + lc);

    u64 qring[8], rring[8];
#pragma unroll
    for (int i = 0; i < 8; ++i) rring[i] = 0;
    qring[0] = pk2(__expf(0.5f * e0v.x), __expf(0.5f * e0v.y));
    u64 qtmp = pk2(__expf(0.5f * e1v.x), __expf(0.5f * e1v.y));   // q_1
    u64 s2   = pk2(__expf(st0 + 0.5f * e0v.x),
                   __expf(st1 + 0.5f * e0v.y));                    // exp(st)*q_0
    u64 P2last = mul2(s2, qring[0]);                               // hatP_0
    if (lane < 24) {
        float px, py; upk(P2last, px, py);
        *(float2*)&Pshf[0][2 * lc] = make_float2(px, py);
    }
    int G = 0;
    __syncwarp();

    // prologue j = 1..7 (start-segment terms active; rescale every step)
#pragma unroll
    for (int j = 1; j < 8; ++j) { STEP(j, j, true, true) }

    // main loop j = 8..511, unrolled x8; rescale at u = 0 and u = 4
    for (int jb = 8; jb < Lc; jb += 8) {
        STEP(jb + 0, 0, true,  false)
        STEP(jb + 1, 1, false, false)
        STEP(jb + 2, 2, false, false)
        STEP(jb + 3, 3, false, false)
        STEP(jb + 4, 4, true,  false)
        STEP(jb + 5, 5, false, false)
        STEP(jb + 6, 6, false, false)
        STEP(jb + 7, 7, false, false)
    }

    // denominator: G*ln2 + log( sum_t hatP_511[t] * exp(end_t[t]) )
    float dv = 0.f;
    if (lane < 24) {
        float px, py; upk(P2last, px, py);
        dv = px * __expf(end_t[t0]) + py * __expf(end_t[t1]);
    }
#pragma unroll
    for (int o = 16; o; o >>= 1) dv += __shfl_xor_sync(0xffffffffu, dv, o);
    const float den = (float)G * 0.6931471805599453f + logf(dv);

    // ---- numerator (this warp) ----
    int c1 = lens[lane * Bc + b];
#pragma unroll
    for (int o = 1; o < 32; o <<= 1) {
        int n = __shfl_up_sync(0xffffffffu, c1, o);
        if (lane >= o) c1 += n;
    }
    const int tot1 = __shfl_sync(0xffffffffu, c1, 31);
    int c2 = (lane + 32 < 64) ? lens[(lane + 32) * Bc + b] : 0;
#pragma unroll
    for (int o = 1; o < 32; o <<= 1) {
        int n = __shfl_up_sync(0xffffffffu, c2, o);
        if (lane >= o) c2 += n;
    }
    c2 += tot1;

    float acc = 0.f;
    {   // segment s = lane (0..31)
        int st = c1; if (st > Lc - 1) st = Lc - 1;
        const int en = st + lens[(lane + 1) * Bc + b];
        const int tg = tags[st * Bc + b];
        const float seg = 0.5f * (em[(st * Bc + b) * Tc + tg] +
                                  em[((en - 1) * Bc + b) * Tc + tg]);
        acc += seg + trans[tags[(st - 1) * Bc + b] * Tc +
                           tags[(en - 1) * Bc + b]];
    }
    if (lane + 32 < 63) {   // segment s = lane+32 (32..62)
        int st = c2; if (st > Lc - 1) st = Lc - 1;
        const int en = st + lens[(lane + 33) * Bc + b];
        const int tg = tags[st * Bc + b];
        const float seg = 0.5f * (em[(st * Bc + b) * Tc + tg] +
                                  em[((en - 1) * Bc + b) * Tc + tg]);
        acc += seg + trans[tags[(st - 1) * Bc + b] * Tc +
                           tags[(en - 1) * Bc + b]];
    }
#pragma unroll
    for (int o = 16; o; o >>= 1) acc += __shfl_xor_sync(0xffffffffu, acc, o);

    if (lane == 0) {
        const int tg0 = tags[b];
        const int l0  = lens[b];
        float sc = start_t[tg0];
        sc += 0.5f * (em[(0 * Bc + b) * Tc + tg0] +
                      em[((l0 - 1) * Bc + b) * Tc + tg0]);
        sc += end_t[tags[(Lc - 1) * Bc + b]];
        g_llh[b] = sc + acc - den;
    }

    // ---- last-block fused final reduction (fixed tree, deterministic) ----
    __threadfence();
    if (lane == 0) isLast = (atomicAdd(&g_cnt, 1) == Bc - 1);
    __syncwarp();
    if (isLast) {
        __threadfence();
        float v = *((volatile float*)&g_llh[lane]);
#pragma unroll
        for (int o = 16; o; o >>= 1) v += __shfl_xor_sync(0xffffffffu, v, o);
        if (lane == 0) { out[0] = v; g_cnt = 0; }
    }
}

extern "C" void kernel_launch(void* const* d_in, const int* in_sizes, int n_in,
                              void* d_out, int out_size) {
    const float* emissions = (const float*)d_in[0];
    const int*   tags      = (const int*)d_in[1];
    const int*   lens      = (const int*)d_in[2];
    // d_in[3] = mask (all ones by construction; unused)
    const float* start_t   = (const float*)d_in[4];
    const float* end_t     = (const float*)d_in[5];
    const float* trans     = (const float*)d_in[6];
    float* out = (float*)d_out;

    semicrf_main_kernel<<<Bc, 32>>>(emissions, tags, lens, start_t, end_t,
                                    trans, out);
}